// round 14
// baseline (speedup 1.0000x reference)
#include <cuda_runtime.h>

#define B40U     0x4B000000u         // bits(2^23)
#define MAG40_F  8388864.0f          // 2^23 + 256
#define NBINS    192                 // 112 core + 76 fringe + 4 dummy
#define NROWS    48
#define NCOARSE  200
#define NTAB     195
#define NHA      196
#define OVCAP    2048
#define GRID_N   592                 // 148 SMs * 4 (48KB smem/block)
#define DUMMYB   188u

__device__ unsigned int g_fh[NBINS];
__device__ float        g_ovv[OVCAP];
__device__ int          g_ovcnt;
__device__ int          g_ovneg;     // max over slow-path elems of -floor(40x); 0 = none-low
__device__ unsigned int g_tick;

struct f8 { float4 a, b; };

static __device__ __forceinline__ f8 ldg8(const float* p) {
    f8 v;
    asm("ld.global.nc.L2::evict_last.v8.b32 {%0,%1,%2,%3,%4,%5,%6,%7}, [%8];"
        : "=f"(v.a.x), "=f"(v.a.y), "=f"(v.a.z), "=f"(v.a.w),
          "=f"(v.b.x), "=f"(v.b.y), "=f"(v.b.z), "=f"(v.b.w)
        : "l"(p));
    return v;
}

// exact slow path for |x| >= 5.2 (expected ~0 elements) and the ragged tail
static __device__ __noinline__ void hov(float f) {
    int idx = atomicAdd(&g_ovcnt, 1);
    if (idx < OVCAP) g_ovv[idx] = f;
    float c = fminf(fmaxf(f * 40.0f, -2.0e9f), 2.0e9f);
    atomicMax(&g_ovneg, -__float2int_rd(c));
}

// bins: core b=floor(40x)+56 in [0,112) for |x|<1.4 (w=1/40)
//       fringe w=1/10: q=floor(10x)+64=(l>>2) in [12,50)u[78,116); b=100+q-(q>=78?28:0) in [112,188)
// all bin boundaries align with table kinks (odd multiples of 0.1) and coarse cells (0.2)
static __device__ __forceinline__ void proc(float x, unsigned char* sh8, unsigned tq) {
    unsigned u = __float_as_uint(__fmaf_rd(x, 40.0f, MAG40_F));
    unsigned l = u - B40U;               // floor(40x)+256; valid iff l-48 < 416
    unsigned b;
    if (l - 48u < 416u) {
        unsigned lc = l - 200u;          // core bin if < 112
        unsigned q  = l >> 2;            // floor(10x)+64 (exact nested floor)
        unsigned f  = 100u + q - (q >= 78u ? 28u : 0u);
        b = (lc < 112u) ? lc : f;
    } else {
        hov(x);
        b = DUMMYB;
    }
    // conflict-free per-thread byte counter: bank = tid&31 always
    sh8[((b & 0xFCu) << 8) | ((b & 3u) | tq)]++;
}

static __device__ __forceinline__ int bin2pos(int b) {   // left edge in 1/40 units
    if (b < 112) return b - 56;
    if (b < 150) return 4 * b - 656;     // fringe low  [-208,-56)
    return 4 * b - 544;                  // fringe high [56,208)
}

__global__ void __launch_bounds__(256) k_fused(const float* __restrict__ xp, int n,
                                               double inv_n, float* __restrict__ out) {
    __shared__ unsigned char sh8[NROWS * 1024];   // 48 KB
    const int tid  = threadIdx.x;
    const int lane = tid & 31;
    const int wid  = tid >> 5;
    const unsigned tq = (unsigned)(tid << 2);

    #pragma unroll
    for (int i = 0; i < NROWS; i++)
        ((unsigned int*)sh8)[i * 256 + tid] = 0u;
    __syncthreads();

    const int n8 = n >> 3;
    const int stride = gridDim.x * blockDim.x;

    for (int i = blockIdx.x * blockDim.x + tid; i < n8; i += stride) {
        f8 v = ldg8(xp + 8 * (long long)i);
        proc(v.a.x, sh8, tq); proc(v.a.y, sh8, tq);
        proc(v.a.z, sh8, tq); proc(v.a.w, sh8, tq);
        proc(v.b.x, sh8, tq); proc(v.b.y, sh8, tq);
        proc(v.b.z, sh8, tq); proc(v.b.w, sh8, tq);
    }
    if (blockIdx.x == 0 && tid < (n & 7)) hov(xp[(n & ~7) + tid]);   // exact tail
    __syncthreads();

    // merge per-thread bytes -> global bins (dp4a per byte lane)
    for (int r = wid; r < NROWS; r += 8) {
        const unsigned int* row = (const unsigned int*)sh8 + r * 256;
        unsigned a0 = 0, a1 = 0, a2 = 0, a3 = 0;
        #pragma unroll
        for (int j = 0; j < 8; j++) {
            unsigned w = row[lane + 32 * j];
            a0 = __dp4a(w, 0x00000001u, a0);
            a1 = __dp4a(w, 0x00000100u, a1);
            a2 = __dp4a(w, 0x00010000u, a2);
            a3 = __dp4a(w, 0x01000000u, a3);
        }
        #pragma unroll
        for (int o = 16; o; o >>= 1) {
            a0 += __shfl_xor_sync(0xFFFFFFFFu, a0, o);
            a1 += __shfl_xor_sync(0xFFFFFFFFu, a1, o);
            a2 += __shfl_xor_sync(0xFFFFFFFFu, a2, o);
            a3 += __shfl_xor_sync(0xFFFFFFFFu, a3, o);
        }
        if (lane == 0) {
            if (a0) atomicAdd(&g_fh[4 * r + 0], a0);
            if (a1) atomicAdd(&g_fh[4 * r + 1], a1);
            if (a2) atomicAdd(&g_fh[4 * r + 2], a2);
            if (a3) atomicAdd(&g_fh[4 * r + 3], a3);
        }
    }
    __syncthreads();

    // ---- ticket: last block runs the epilogue ----
    __shared__ unsigned int s_islast;
    if (tid == 0) {
        __threadfence();
        s_islast = (atomicInc(&g_tick, gridDim.x - 1) == gridDim.x - 1);
    }
    __syncthreads();
    if (!s_islast) return;

    // ======== epilogue: everything from the fine histogram ========
    // alias small arrays into sh8 (contents no longer needed)
    unsigned* s_cnt  = (unsigned*)(sh8 + 0);        // [192]
    unsigned* s_c    = (unsigned*)(sh8 + 768);      // [200]
    unsigned* s_cum  = (unsigned*)(sh8 + 1568);     // [200]
    float*    s_ha   = (float*)   (sh8 + 2368);     // [196]
    float2*   s_tab  = (float2*)  (sh8 + 3152);     // [195]
    double*   s_red  = (double*)  (sh8 + 4712);     // [8]
    int*      s_misc = (int*)     (sh8 + 4776);     // [8]
    unsigned* s_wsum = (unsigned*)(sh8 + 4808);     // [8]

    if (tid < NBINS) { unsigned c = g_fh[tid]; g_fh[tid] = 0u; s_cnt[tid] = c; }
    if (tid == 0) {
        int ovn   = atomicExch(&g_ovcnt, 0);
        int ovneg = atomicExch(&g_ovneg, 0);
        s_misc[2] = min(ovn, OVCAP);
        s_misc[0] = (ovneg > 0) ? -ovneg : 0x7FFFFFFF;   // min floor(40x) candidate
    }
    __syncthreads();

    // min position over nonempty fine bins
    if (tid < (int)DUMMYB && s_cnt[tid]) atomicMin(&s_misc[0], bin2pos(tid));
    __syncthreads();
    if (tid == 0) {
        int mp = s_misc[0];
        int fd = (mp >= 0) ? mp / 40 : -((-mp + 39) / 40);   // floor(xmin)
        s_misc[1] = fd - 1;                                   // vmin
    }
    if (tid < NCOARSE) s_c[tid] = 0u;
    __syncthreads();
    const int vmin = s_misc[1];
    const int ovn  = s_misc[2];

    // coarse histc (fine bins nest exactly in 0.2-wide coarse cells)
    if (tid < (int)DUMMYB && s_cnt[tid]) {
        int j = (bin2pos(tid) - 40 * vmin) >> 3;
        j = max(0, min(j, NCOARSE - 1));
        atomicAdd(&s_c[j], s_cnt[tid]);
    }
    for (int k = tid; k < ovn; k += 256) {
        float v = g_ovv[k];
        float c5 = fminf(fmaxf(v * 5.0f, -2.0e9f), 2.0e9f);
        int j = __float2int_rd(c5) - 5 * vmin;
        j = max(0, min(j, NCOARSE - 1));
        atomicAdd(&s_c[j], 1u);
    }
    __syncthreads();

    // inclusive scan of 200 coarse bins
    {
        unsigned v = (tid < NCOARSE) ? s_c[tid] : 0u;
        unsigned x = v;
        #pragma unroll
        for (int o = 1; o < 32; o <<= 1) {
            unsigned y = __shfl_up_sync(0xFFFFFFFFu, x, o);
            if (lane >= o) x += y;
        }
        if (lane == 31) s_wsum[wid] = x;
        __syncthreads();
        if (tid == 0) {
            unsigned a = 0;
            #pragma unroll
            for (int w = 0; w < 8; w++) { unsigned t = s_wsum[w]; s_wsum[w] = a; a += t; }
        }
        __syncthreads();
        if (tid < NCOARSE) s_cum[tid] = x + s_wsum[wid];
        __syncthreads();
    }

    // hist_add + table
    const unsigned total = s_cum[NCOARSE - 1];
    if (tid < NHA) {
        double lo = (tid == 0) ? 0.0 : (double)s_cum[tid - 1];
        double hi = (tid >= NHA - 1) ? (double)total : (double)s_cum[tid + 4];
        s_ha[tid] = (float)((hi - lo) * inv_n);
    }
    __syncthreads();
    if (tid < NTAB) {
        float A = s_ha[tid + 1] - s_ha[tid];
        float B = (float)((double)s_ha[tid] + 1e-8 - (double)tid * (double)A);
        s_tab[tid] = make_float2(A, B);
    }
    __syncthreads();

    // loss: binned midpoints + exact overflow terms
    const float nvmn5 = -(5.0f * (float)vmin + 2.5f);
    double sum = 0.0;
    if (tid < (int)DUMMYB && s_cnt[tid]) {
        int pos = bin2pos(tid);
        double h = (tid < 112) ? 0.5 : 2.0;
        double td = ((double)pos + h) * 0.125 - 5.0 * (double)vmin - 2.5;   // >= 2.5
        int i = min((int)td, NTAB - 1);
        float2 ab = s_tab[i];
        float nl = fmaf((float)td, ab.x, ab.y);
        sum += (double)s_cnt[tid] * log2((double)nl);
    }
    for (int k = tid; k < ovn; k += 256) {
        float v = g_ovv[k];
        float t = fmaf(v, 5.0f, nvmn5);
        int i = max(0, min((int)t, NTAB - 1));
        float2 ab = s_tab[i];
        sum += log2((double)fmaf(t, ab.x, ab.y));
    }

    // reduce doubles across the block
    #pragma unroll
    for (int o = 16; o; o >>= 1) sum += __shfl_xor_sync(0xFFFFFFFFu, sum, o);
    if (lane == 0) s_red[wid] = sum;
    __syncthreads();
    if (tid == 0) {
        double a = 0.0;
        #pragma unroll
        for (int w = 0; w < 8; w++) a += s_red[w];
        out[0] = (float)(-a * inv_n);
    }
}

// ---------------------------------------------------------------- launch
extern "C" void kernel_launch(void* const* d_in, const int* in_sizes, int n_in,
                              void* d_out, int out_size) {
    const float* x = (const float*)d_in[0];
    const int n = in_sizes[0];
    const double inv_n = 1.0 / (double)n;

    k_fused<<<GRID_N, 256>>>(x, n, inv_n, (float*)d_out);
}